// round 2
// baseline (speedup 1.0000x reference)
#include <cuda_runtime.h>
#include <cuda_bf16.h>
#include <cstddef>

#define S_DET 725
#define S_ANG 360
#define IMG   512
#define NNZ   8388608LL
#define NB    4

// Scratch (device globals; no cudaMalloc allowed)
#define ACTN (4ULL*512*512*64)          // 67,108,864 floats (covers sinogram 66,816,000 too)
__device__ float g_A[ACTN];
__device__ float g_B[ACTN];
__device__ float g_C[ACTN];
__device__ float g_filtT[S_DET*S_ANG*4];   // [col][b]
__device__ float g_fbpT[IMG*IMG*4];        // [pix][b] accumulators
__device__ float g_fbp[4*IMG*IMG];         // [b][pix]

// ---------------------------------------------------------------------------
// conv 5x5, Cin=1 -> Cout=64, +bias, ReLU; writes y and pp (pp = y)
// grid: (ceil(W/8), ceil(H/8), B), block 256
// ---------------------------------------------------------------------------
__global__ void __launch_bounds__(256) conv_first(
    const float* __restrict__ x, const float* __restrict__ w,
    const float* __restrict__ bias,
    float* __restrict__ y, float* __restrict__ pp, int H, int W)
{
    __shared__ float xs[12*12];
    __shared__ float ws[25*64];
    const int t = threadIdx.x;
    const int b = blockIdx.z;
    const int x0 = blockIdx.x*8 - 2, y0 = blockIdx.y*8 - 2;
    const float* xb = x + (size_t)b*H*W;
    if (t < 144) {
        int yy = y0 + t/12, xx = x0 + t%12;
        xs[t] = ((unsigned)yy < (unsigned)H && (unsigned)xx < (unsigned)W)
                ? xb[(size_t)yy*W + xx] : 0.f;
    }
    for (int i = t; i < 1600; i += 256) ws[i] = w[i];
    __syncthreads();

    const int cg = t & 15, pg = t >> 4;
    const int co0 = cg*4;
    int py[4], px[4];
    #pragma unroll
    for (int k = 0; k < 4; ++k) { int p = pg + 16*k; py[k] = p >> 3; px[k] = p & 7; }
    float acc[4][4];
    #pragma unroll
    for (int k = 0; k < 4; ++k)
        #pragma unroll
        for (int j = 0; j < 4; ++j) acc[k][j] = 0.f;

    #pragma unroll
    for (int tap = 0; tap < 25; ++tap) {
        const int dy = tap/5, dx = tap - 5*(tap/5);
        const float4 wv = *(const float4*)(ws + tap*64 + co0);
        #pragma unroll
        for (int k = 0; k < 4; ++k) {
            float a = xs[(py[k]+dy)*12 + px[k]+dx];
            acc[k][0] = fmaf(a, wv.x, acc[k][0]);
            acc[k][1] = fmaf(a, wv.y, acc[k][1]);
            acc[k][2] = fmaf(a, wv.z, acc[k][2]);
            acc[k][3] = fmaf(a, wv.w, acc[k][3]);
        }
    }

    const int gx0 = blockIdx.x*8, gy0 = blockIdx.y*8;
    float bs[4];
    #pragma unroll
    for (int j = 0; j < 4; ++j) bs[j] = bias[co0+j];
    #pragma unroll
    for (int k = 0; k < 4; ++k) {
        int gy = gy0 + py[k], gx = gx0 + px[k];
        if (gy < H && gx < W) {
            size_t off = (((size_t)b*H + gy)*W + gx)*64 + co0;
            float4 r;
            r.x = fmaxf(acc[k][0] + bs[0], 0.f);
            r.y = fmaxf(acc[k][1] + bs[1], 0.f);
            r.z = fmaxf(acc[k][2] + bs[2], 0.f);
            r.w = fmaxf(acc[k][3] + bs[3], 0.f);
            *(float4*)(y + off)  = r;
            *(float4*)(pp + off) = r;
        }
    }
}

// ---------------------------------------------------------------------------
// conv 5x5 64->64 + BN + ReLU; y = result, pp += result
// dynamic smem: 12*12*64 + 2*64*64 floats = 69632 B (ping-pong weight panels)
// ---------------------------------------------------------------------------
__global__ void __launch_bounds__(256) conv_mid(
    const float* __restrict__ x, const float* __restrict__ w,
    const float* __restrict__ gamma, const float* __restrict__ beta,
    const float* __restrict__ mean, const float* __restrict__ var,
    float* __restrict__ y, float* __restrict__ pp, int H, int W)
{
    extern __shared__ float smem[];
    float* xs = smem;            // 9216
    float* wbuf = smem + 9216;   // 2 * 4096
    const int t = threadIdx.x;
    const int b = blockIdx.z;
    const int x0 = blockIdx.x*8 - 2, y0 = blockIdx.y*8 - 2;
    const float* xb = x + (size_t)b*H*W*64;

    // stage input tile
    float4* xs4 = (float4*)xs;
    for (int i = t; i < 12*12*16; i += 256) {
        int p = i >> 4, c4 = i & 15;
        int yy = y0 + p/12, xx = x0 + p - 12*(p/12);
        float4 v = make_float4(0.f,0.f,0.f,0.f);
        if ((unsigned)yy < (unsigned)H && (unsigned)xx < (unsigned)W)
            v = *(const float4*)(xb + ((size_t)yy*W + xx)*64 + c4*4);
        xs4[i] = v;
    }
    // stage tap-0 weights into buffer 0
    {
        const float4* wsrc = (const float4*)w;
        float4* wd = (float4*)wbuf;
        #pragma unroll
        for (int j = 0; j < 4; ++j) wd[t + j*256] = wsrc[t + j*256];
    }
    __syncthreads();

    const int cg = t & 15, pg = t >> 4;
    const int co0 = cg*4;
    int py[4], px[4];
    #pragma unroll
    for (int k = 0; k < 4; ++k) { int p = pg + 16*k; py[k] = p >> 3; px[k] = p & 7; }
    float acc[4][4];
    #pragma unroll
    for (int k = 0; k < 4; ++k)
        #pragma unroll
        for (int j = 0; j < 4; ++j) acc[k][j] = 0.f;

    for (int tap = 0; tap < 25; ++tap) {
        float* ws = wbuf + (tap & 1)*4096;
        // prefetch next tap's weights into the other buffer (no barrier needed
        // before: consumers of that buffer synced at the END of previous iter)
        float4 pf[4];
        if (tap < 24) {
            const float4* wsrc = (const float4*)(w + (size_t)(tap+1)*4096);
            #pragma unroll
            for (int j = 0; j < 4; ++j) pf[j] = wsrc[t + j*256];
        }
        const int dy = tap/5, dx = tap - 5*(tap/5);
        const int o0 = ((py[0]+dy)*12 + px[0]+dx)*64;
        const int o1 = ((py[1]+dy)*12 + px[1]+dx)*64;
        const int o2 = ((py[2]+dy)*12 + px[2]+dx)*64;
        const int o3 = ((py[3]+dy)*12 + px[3]+dx)*64;
        #pragma unroll 16
        for (int ci = 0; ci < 64; ++ci) {
            const float4 wv = *(const float4*)(ws + (ci<<6) + co0);
            const float a0 = xs[o0+ci];
            const float a1 = xs[o1+ci];
            const float a2 = xs[o2+ci];
            const float a3 = xs[o3+ci];
            acc[0][0]=fmaf(a0,wv.x,acc[0][0]); acc[0][1]=fmaf(a0,wv.y,acc[0][1]);
            acc[0][2]=fmaf(a0,wv.z,acc[0][2]); acc[0][3]=fmaf(a0,wv.w,acc[0][3]);
            acc[1][0]=fmaf(a1,wv.x,acc[1][0]); acc[1][1]=fmaf(a1,wv.y,acc[1][1]);
            acc[1][2]=fmaf(a1,wv.z,acc[1][2]); acc[1][3]=fmaf(a1,wv.w,acc[1][3]);
            acc[2][0]=fmaf(a2,wv.x,acc[2][0]); acc[2][1]=fmaf(a2,wv.y,acc[2][1]);
            acc[2][2]=fmaf(a2,wv.z,acc[2][2]); acc[2][3]=fmaf(a2,wv.w,acc[2][3]);
            acc[3][0]=fmaf(a3,wv.x,acc[3][0]); acc[3][1]=fmaf(a3,wv.y,acc[3][1]);
            acc[3][2]=fmaf(a3,wv.z,acc[3][2]); acc[3][3]=fmaf(a3,wv.w,acc[3][3]);
        }
        if (tap < 24) {
            float4* wd = (float4*)(wbuf + ((tap+1) & 1)*4096);
            #pragma unroll
            for (int j = 0; j < 4; ++j) wd[t + j*256] = pf[j];
            __syncthreads();
        }
    }

    float sc[4], bs[4];
    #pragma unroll
    for (int j = 0; j < 4; ++j) {
        float g = gamma[co0+j];
        sc[j] = g * rsqrtf(var[co0+j] + 1e-3f);
        bs[j] = beta[co0+j] - mean[co0+j]*sc[j];
    }
    const int gx0 = blockIdx.x*8, gy0 = blockIdx.y*8;
    #pragma unroll
    for (int k = 0; k < 4; ++k) {
        int gy = gy0 + py[k], gx = gx0 + px[k];
        if (gy < H && gx < W) {
            size_t off = (((size_t)b*H + gy)*W + gx)*64 + co0;
            float4 r;
            r.x = fmaxf(fmaf(acc[k][0], sc[0], bs[0]), 0.f);
            r.y = fmaxf(fmaf(acc[k][1], sc[1], bs[1]), 0.f);
            r.z = fmaxf(fmaf(acc[k][2], sc[2], bs[2]), 0.f);
            r.w = fmaxf(fmaf(acc[k][3], sc[3], bs[3]), 0.f);
            *(float4*)(y + off) = r;
            float4 pv = *(float4*)(pp + off);
            pv.x += r.x; pv.y += r.y; pv.z += r.z; pv.w += r.w;
            *(float4*)(pp + off) = pv;
        }
    }
}

// ---------------------------------------------------------------------------
// conv 5x5 64->1: out = conv(pp)*invM + bias + res
// grid (ceil(W/16), ceil(H/16), B), block 256; dyn smem (25600+1600)*4 = 108800B
// ---------------------------------------------------------------------------
__global__ void __launch_bounds__(256) conv_last(
    const float* __restrict__ ppin, const float* __restrict__ w,
    const float* __restrict__ bias, const float* __restrict__ res,
    float* __restrict__ out, int H, int W, float invM)
{
    extern __shared__ float smem[];
    float* xs = smem;            // 20*20*64 = 25600
    float* ws = smem + 25600;    // 1600
    const int t = threadIdx.x;
    const int b = blockIdx.z;
    const int x0 = blockIdx.x*16 - 2, y0 = blockIdx.y*16 - 2;
    const float* xb = ppin + (size_t)b*H*W*64;

    float4* xs4 = (float4*)xs;
    for (int i = t; i < 20*20*16; i += 256) {
        int p = i >> 4, c4 = i & 15;
        int yy = y0 + p/20, xx = x0 + p - 20*(p/20);
        float4 v = make_float4(0.f,0.f,0.f,0.f);
        if ((unsigned)yy < (unsigned)H && (unsigned)xx < (unsigned)W)
            v = *(const float4*)(xb + ((size_t)yy*W + xx)*64 + c4*4);
        xs4[i] = v;
    }
    for (int i = t; i < 1600; i += 256) ws[i] = w[i];
    __syncthreads();

    const int ty = t >> 4, tx = t & 15;
    const int gy = blockIdx.y*16 + ty, gx = blockIdx.x*16 + tx;
    if (gy >= H || gx >= W) return;
    float acc = 0.f;
    for (int tap = 0; tap < 25; ++tap) {
        const int dy = tap/5, dx = tap - 5*(tap/5);
        const float4* xv = (const float4*)(xs + ((ty+dy)*20 + tx+dx)*64);
        const float4* wv = (const float4*)(ws + tap*64);
        #pragma unroll
        for (int c4 = 0; c4 < 16; ++c4) {
            float4 a = xv[c4], q = wv[c4];
            acc = fmaf(a.x, q.x, acc);
            acc = fmaf(a.y, q.y, acc);
            acc = fmaf(a.z, q.z, acc);
            acc = fmaf(a.w, q.w, acc);
        }
    }
    size_t pix = ((size_t)b*H + gy)*W + gx;
    out[pix] = fmaf(acc, invM, bias[0]) + res[pix];
}

// ---------------------------------------------------------------------------
// ramp filter: for (b, ang): filtT[(ang*725+n)*4+b] = sum_k wb[k]*desin_pad[n+k]
// grid 1440 (b*360+ang), block 736
// ---------------------------------------------------------------------------
__global__ void __launch_bounds__(736) filter_kernel(
    const float* __restrict__ de_sin, const float* __restrict__ wb,
    float* __restrict__ filtT)
{
    __shared__ float xs[S_DET + S_DET - 1];  // 1449, zero padded
    __shared__ float wbs[S_DET];
    const int t = threadIdx.x;
    const int blk = blockIdx.x;
    const int b = blk / S_ANG, ang = blk - b*S_ANG;
    for (int i = t; i < 2*S_DET-1; i += 736) xs[i] = 0.f;
    if (t < S_DET) wbs[t] = wb[t];
    __syncthreads();
    if (t < S_DET)
        xs[362 + t] = de_sin[((size_t)b*S_DET + t)*S_ANG + ang];
    __syncthreads();
    if (t < S_DET) {
        float acc = 0.f;
        #pragma unroll 5
        for (int k = 0; k < S_DET; ++k)
            acc = fmaf(wbs[k], xs[t + k], acc);
        filtT[((size_t)ang*S_DET + t)*4 + b] = acc;
    }
}

// ---------------------------------------------------------------------------
// sparse backprojection: rows sorted; 16 nnz per thread, register accumulate,
// atomicAdd only on row change.
// ---------------------------------------------------------------------------
__global__ void __launch_bounds__(256) backproj(
    const float* __restrict__ vals, const int* __restrict__ rows,
    const int* __restrict__ cols, const float4* __restrict__ filtT,
    float* __restrict__ fbpT)
{
    const long long s = ((long long)blockIdx.x*blockDim.x + threadIdx.x) * 16;
    if (s >= NNZ) return;
    int cur = rows[s];
    float a0 = 0.f, a1 = 0.f, a2 = 0.f, a3 = 0.f;
    #pragma unroll 4
    for (int j = 0; j < 16; ++j) {
        const long long i = s + j;
        const int r = rows[i];
        if (r != cur) {
            atomicAdd(&fbpT[(size_t)cur*4+0], a0);
            atomicAdd(&fbpT[(size_t)cur*4+1], a1);
            atomicAdd(&fbpT[(size_t)cur*4+2], a2);
            atomicAdd(&fbpT[(size_t)cur*4+3], a3);
            cur = r; a0 = a1 = a2 = a3 = 0.f;
        }
        const float v = vals[i];
        const float4 f = filtT[cols[i]];
        a0 = fmaf(v, f.x, a0);
        a1 = fmaf(v, f.y, a1);
        a2 = fmaf(v, f.z, a2);
        a3 = fmaf(v, f.w, a3);
    }
    atomicAdd(&fbpT[(size_t)cur*4+0], a0);
    atomicAdd(&fbpT[(size_t)cur*4+1], a1);
    atomicAdd(&fbpT[(size_t)cur*4+2], a2);
    atomicAdd(&fbpT[(size_t)cur*4+3], a3);
}

__global__ void __launch_bounds__(256) fbp_fin(
    const float* __restrict__ fbpT, float* __restrict__ fbp,
    float* __restrict__ out_fbp)
{
    const int i = blockIdx.x*blockDim.x + threadIdx.x;
    if (i >= IMG*IMG) return;
    const float4 v = *(const float4*)(fbpT + (size_t)i*4);
    const float r0 = 4.f*v.x, r1 = 4.f*v.y, r2 = 4.f*v.z, r3 = 4.f*v.w;
    fbp[0*IMG*IMG + i] = r0;  out_fbp[0*IMG*IMG + i] = r0;
    fbp[1*IMG*IMG + i] = r1;  out_fbp[1*IMG*IMG + i] = r1;
    fbp[2*IMG*IMG + i] = r2;  out_fbp[2*IMG*IMG + i] = r2;
    fbp[3*IMG*IMG + i] = r3;  out_fbp[3*IMG*IMG + i] = r3;
}

// ---------------------------------------------------------------------------
extern "C" void kernel_launch(void* const* d_in, const int* in_sizes, int n_in,
                              void* d_out, int out_size)
{
    const float* inputs    = (const float*)d_in[0];
    const float* w_sin1    = (const float*)d_in[1];
    const float* b_sin1    = (const float*)d_in[2];
    const float* w_sin_mid = (const float*)d_in[3];
    const float* sin_gamma = (const float*)d_in[4];
    const float* sin_beta  = (const float*)d_in[5];
    const float* sin_mean  = (const float*)d_in[6];
    const float* sin_var   = (const float*)d_in[7];
    const float* w_sin6    = (const float*)d_in[8];
    const float* b_sin6    = (const float*)d_in[9];
    const float* w_ct1     = (const float*)d_in[10];
    const float* b_ct1     = (const float*)d_in[11];
    const float* w_ct_mid  = (const float*)d_in[12];
    const float* ct_gamma  = (const float*)d_in[13];
    const float* ct_beta   = (const float*)d_in[14];
    const float* ct_mean   = (const float*)d_in[15];
    const float* ct_var    = (const float*)d_in[16];
    const float* w_ct6     = (const float*)d_in[17];
    const float* b_ct6     = (const float*)d_in[18];
    const float* w_b       = (const float*)d_in[19];
    const float* at_vals   = (const float*)d_in[20];
    const int*   at_rows   = (const int*)d_in[21];
    const int*   at_cols   = (const int*)d_in[22];

    float *pA, *pB, *pC, *pFiltT, *pFbpT, *pFbp;
    cudaGetSymbolAddress((void**)&pA, g_A);
    cudaGetSymbolAddress((void**)&pB, g_B);
    cudaGetSymbolAddress((void**)&pC, g_C);
    cudaGetSymbolAddress((void**)&pFiltT, g_filtT);
    cudaGetSymbolAddress((void**)&pFbpT, g_fbpT);
    cudaGetSymbolAddress((void**)&pFbp, g_fbp);

    cudaFuncSetAttribute(conv_mid,  cudaFuncAttributeMaxDynamicSharedMemorySize, 69632);
    cudaFuncSetAttribute(conv_last, cudaFuncAttributeMaxDynamicSharedMemorySize, 108800);

    float* out_desin = (float*)d_out;                      // [4,725,360]
    float* out_img   = out_desin + 4*S_DET*S_ANG;          // [4,512,512]
    float* out_fbp   = out_img + 4*IMG*IMG;                // [4,512,512]

    // --- sinogram CNN ---
    {
        dim3 gs((S_ANG+7)/8, (S_DET+7)/8, NB);   // 45 x 91 x 4
        conv_first<<<gs, 256>>>(inputs, w_sin1, b_sin1, pA, pB, S_DET, S_ANG);
        float* cur = pA; float* nxt = pC;
        for (int i = 0; i < 4; ++i) {
            conv_mid<<<gs, 256, 69632>>>(cur, w_sin_mid + (size_t)i*25*64*64,
                                         sin_gamma + i*64, sin_beta + i*64,
                                         sin_mean + i*64, sin_var + i*64,
                                         nxt, pB, S_DET, S_ANG);
            float* tmp = cur; cur = nxt; nxt = tmp;
        }
        dim3 gs2((S_ANG+15)/16, (S_DET+15)/16, NB);  // 23 x 46 x 4
        conv_last<<<gs2, 256, 108800>>>(pB, w_sin6, b_sin6, inputs, out_desin,
                                        S_DET, S_ANG, 0.25f);
    }

    // --- FBP decode ---
    filter_kernel<<<NB*S_ANG, 736>>>(out_desin, w_b, pFiltT);
    cudaMemsetAsync(pFbpT, 0, (size_t)IMG*IMG*4*sizeof(float));
    backproj<<<(int)(NNZ/16/256), 256>>>(at_vals, at_rows, at_cols,
                                         (const float4*)pFiltT, pFbpT);
    fbp_fin<<<(IMG*IMG+255)/256, 256>>>(pFbpT, pFbp, out_fbp);

    // --- image CNN ---
    {
        dim3 gi(IMG/8, IMG/8, NB);   // 64 x 64 x 4
        conv_first<<<gi, 256>>>(pFbp, w_ct1, b_ct1, pA, pB, IMG, IMG);
        float* cur = pA; float* nxt = pC;
        for (int i = 0; i < 5; ++i) {
            conv_mid<<<gi, 256, 69632>>>(cur, w_ct_mid + (size_t)i*25*64*64,
                                         ct_gamma + i*64, ct_beta + i*64,
                                         ct_mean + i*64, ct_var + i*64,
                                         nxt, pB, IMG, IMG);
            float* tmp = cur; cur = nxt; nxt = tmp;
        }
        dim3 gi2(IMG/16, IMG/16, NB);  // 32 x 32 x 4
        conv_last<<<gi2, 256, 108800>>>(pB, w_ct6, b_ct6, pFbp, out_img,
                                        IMG, IMG, 0.2f);
    }
}